// round 12
// baseline (speedup 1.0000x reference)
#include <cuda_runtime.h>
#include <cuda_bf16.h>
#include <cuda_fp16.h>
#include <math.h>
#include <stdint.h>

#define B_  2
#define S_  2048
#define H_  2048
#define NH_ 16
#define HD_ 128
#define M_  (B_*S_)   // 4096

// ---------------- scratch (device globals) ---------------------------------
__device__ float g_cos[S_*64];
__device__ float g_sin[S_*64];

__device__ __align__(16) __half g_Af[M_*H_];          // activations fp16
__device__ __align__(16) __half g_Bqk[2*H_*H_];       // Wq^T, Wk^T fp16
__device__ __align__(16) __half g_Bf[H_*H_];          // Wv^T fp16
__device__ __align__(16) __half g_Wf[H_*H_];          // Wo^T fp16

// attention operands
__device__ __align__(16) __half g_qf[B_*NH_*S_*HD_];  // roped Q fp16
__device__ __align__(16) __half g_kf[B_*NH_*S_*HD_];  // roped K fp16
__device__ __align__(16) __half g_vtf[B_*NH_*HD_*S_]; // V^T fp16

// ---------------- PTX helpers ----------------------------------------------
__device__ __forceinline__ uint32_t smem_u32(const void* p) {
    uint32_t a;
    asm("{ .reg .u64 t; cvta.to.shared.u64 t, %1; cvt.u32.u64 %0, t; }"
        : "=r"(a) : "l"(p));
    return a;
}
#define CP16(dst, src) \
    asm volatile("cp.async.cg.shared.global [%0], [%1], 16;" \
                 :: "r"(dst), "l"(src) : "memory")
#define CP_COMMIT() asm volatile("cp.async.commit_group;" ::: "memory")

#define LDM4(r, addr) \
    asm volatile("ldmatrix.sync.aligned.m8n8.x4.shared.b16 {%0,%1,%2,%3}, [%4];" \
        : "=r"((r)[0]), "=r"((r)[1]), "=r"((r)[2]), "=r"((r)[3]) : "r"(addr))

__device__ __forceinline__ void mma_f16(float* d, const uint32_t* a,
                                        uint32_t b0, uint32_t b1) {
    asm volatile("mma.sync.aligned.m16n8k16.row.col.f32.f16.f16.f32 "
        "{%0,%1,%2,%3}, {%4,%5,%6,%7}, {%8,%9}, {%0,%1,%2,%3};"
        : "+f"(d[0]), "+f"(d[1]), "+f"(d[2]), "+f"(d[3])
        : "r"(a[0]), "r"(a[1]), "r"(a[2]), "r"(a[3]), "r"(b0), "r"(b1));
}
__device__ __forceinline__ uint32_t packhf(float x, float y) {
    __half2 t = __floats2half2_rn(x, y);
    return *(uint32_t*)&t;
}

// ---------------- prep kernels ---------------------------------------------
__global__ void rope_table_kernel()
{
    int idx = blockIdx.x * blockDim.x + threadIdx.x;
    if (idx >= S_ * 64) return;
    int s = idx >> 6, p = idx & 63;
    double invf = exp(-log(10000.0) * (double)p / 64.0);
    double ang  = (double)s * invf;
    g_cos[idx] = (float)cos(ang);
    g_sin[idx] = (float)sin(ang);
}

// fp32 X -> fp16 g_Af
__global__ void convert_f16_kernel(const float* __restrict__ in)
{
    int i = (blockIdx.x * blockDim.x + threadIdx.x) * 4;
    float4 v = *(const float4*)&in[i];
    *(ushort4*)((unsigned short*)g_Af + i) = make_ushort4(
        __half_as_ushort(__float2half_rn(v.x)),
        __half_as_ushort(__float2half_rn(v.y)),
        __half_as_ushort(__float2half_rn(v.z)),
        __half_as_ushort(__float2half_rn(v.w)));
}

// all four W [2048,2048] -> W^T fp16 in one launch (blockIdx.z selects)
__global__ void transpose_f16_kernel(const float* __restrict__ Wq,
                                     const float* __restrict__ Wk,
                                     const float* __restrict__ Wv,
                                     const float* __restrict__ Wo)
{
    int which = blockIdx.z;
    const float* in = (which == 0) ? Wq : (which == 1) ? Wk
                    : (which == 2) ? Wv : Wo;
    __half* dst = (which < 2) ? g_Bqk + (size_t)which*H_*H_
                : (which == 2) ? g_Bf : g_Wf;
    __shared__ float t[32][33];
    int tx = threadIdx.x, ty = threadIdx.y;
    int c0 = blockIdx.x * 32, r0 = blockIdx.y * 32;
#pragma unroll
    for (int k = 0; k < 4; k++)
        t[ty + 8*k][tx] = in[(size_t)(r0 + ty + 8*k) * H_ + c0 + tx];
    __syncthreads();
#pragma unroll
    for (int k = 0; k < 4; k++)
        dst[(size_t)(c0 + ty + 8*k) * H_ + r0 + tx] =
            __float2half_rn(t[tx][ty + 8*k]);
}

// ---------------- fp16 GEMM mainloop ----------------------------------------
// CTA tile 128x128, 128 threads (4 warps), warp tile 64M x 64N (split cols).
// 64B swizzled rows: phys = r*64 + 16*(g ^ ((r>>1)&3)).
// 6 stages, one barrier per TWO 32-K chunks.
// Inner loop: p-outer with double-buffered B fragments so the ldmatrix->mma
// dependency is pipelined in SOURCE (reg ceiling cannot defeat it).
#define REG_B  8192              // 128 rows x 64B
#define FSTG_B (2*REG_B)         // A|B regions = 16384
#define SMEM_GF (6*FSTG_B)       // 98304

__device__ __forceinline__ void ld_region(uint32_t dst,
    const __half* __restrict__ src, int row0, int kb, int tid)
{
#pragma unroll
    for (int it = 0; it < 4; it++) {
        int idx = tid + it*128;           // 512 granules
        int r = idx >> 2, g = idx & 3;
        uint32_t sw = (uint32_t)((g ^ ((r >> 1) & 3)) << 4);
        CP16(dst + r*64 + sw,
             (const void*)(src + (size_t)(row0 + r) * H_ + kb + g*8));
    }
}
__device__ __forceinline__ void ld_stage_f16(uint32_t s0,
    const __half* A, const __half* Bm, int m0, int n0, int kb, int tid)
{
    ld_region(s0,         A,  m0, kb, tid);
    ld_region(s0 + REG_B, Bm, n0, kb, tid);
    CP_COMMIT();
}

// acc[mi][nj][4]: rows (w>>1)*64 + mi*16 (+lane), cols (w&1)*32 + (nj&3)*8
// (+64 for nj>=4)
__device__ __forceinline__ void hmma_mainloop_f16(
    const __half* A, const __half* Bm,
    int m0, int n0, uint32_t sb, float acc[4][8][4])
{
    const int tid = threadIdx.x, lane = tid & 31, w = tid >> 5;
#pragma unroll
    for (int i = 0; i < 4; i++)
#pragma unroll
        for (int j = 0; j < 8; j++)
#pragma unroll
            for (int k = 0; k < 4; k++) acc[i][j][k] = 0.f;

    // prologue: chunks 0..3 into slots 0..3
    ld_stage_f16(sb + 0*FSTG_B, A, Bm, m0, n0, 0,  tid);
    ld_stage_f16(sb + 1*FSTG_B, A, Bm, m0, n0, 32, tid);
    ld_stage_f16(sb + 2*FSTG_B, A, Bm, m0, n0, 64, tid);
    ld_stage_f16(sb + 3*FSTG_B, A, Bm, m0, n0, 96, tid);

    const int hi  = lane >> 4;            // 16B column select
    const int rsw = (lane >> 1) & 3;      // swizzle const (same for all rows)
    const uint32_t swz0 = (uint32_t)(((0 + hi) ^ rsw) << 4);   // kk=0
    const uint32_t swz1 = (uint32_t)(((2 + hi) ^ rsw) << 4);   // kk=1
    const uint32_t arow64 = (uint32_t)(((w >> 1)*64 + (lane & 15)) * 64);
    const uint32_t brow64 = (uint32_t)(((w & 1)*32 + (lane & 15)) * 64);

    for (int i = 0; i < 32; i++) {
        const int cA = 2*i;
        if (i < 31) asm volatile("cp.async.wait_group 2;" ::: "memory");
        else        asm volatile("cp.async.wait_group 0;" ::: "memory");
        __syncthreads();
        if (cA + 4 < 64) {
            ld_stage_f16(sb + ((cA+4)%6)*FSTG_B, A, Bm, m0, n0, (cA+4)*32, tid);
            ld_stage_f16(sb + ((cA+5)%6)*FSTG_B, A, Bm, m0, n0, (cA+5)*32, tid);
        }
#pragma unroll
        for (int cc = 0; cc < 2; cc++) {
            uint32_t s0 = sb + (uint32_t)(((cA + cc) % 6) * FSTG_B);
#pragma unroll
            for (int kk = 0; kk < 2; kk++) {
                uint32_t swz = kk ? swz1 : swz0;
                uint32_t a[4][4];
#pragma unroll
                for (int mi = 0; mi < 4; mi++)
                    LDM4(a[mi], s0 + arow64 + (uint32_t)(mi*1024) + swz);
                // double-buffered B fragments: q[(p+1)&1] loads while
                // q[p&1] feeds 8 MMAs
                uint32_t q[2][4];
                LDM4(q[0], s0 + REG_B + brow64 + swz);          // p = 0
#pragma unroll
                for (int p = 0; p < 4; p++) {
                    if (p < 3) {
                        uint32_t roff = (uint32_t)(
                            (((p+1) & 1)*16 + (((p+1) & 2) ? 64 : 0)) * 64);
                        LDM4(q[(p+1) & 1], s0 + REG_B + brow64 + roff + swz);
                    }
                    const uint32_t* qq = q[p & 1];
#pragma unroll
                    for (int mi = 0; mi < 4; mi++) {
                        mma_f16(acc[mi][2*p],   a[mi], qq[0], qq[2]);
                        mma_f16(acc[mi][2*p+1], a[mi], qq[1], qq[3]);
                    }
                }
            }
        }
    }
}

// ---------------- QKV projection + bias (+RoPE) -> fp16 ---------------------
// grid (48, 32): z = x>>4 (0=q,1=k,2=v), nh = x&15 ; y -> m-tile
__global__ __launch_bounds__(128, 2)
void gemm_qkv_f16(const float* __restrict__ bq, const float* __restrict__ bk,
                  const float* __restrict__ bv)
{
    extern __shared__ char dsm[];
    uint32_t sb = smem_u32(dsm);
    const int tid = threadIdx.x, lane = tid & 31, w = tid >> 5;
    const int z = blockIdx.x >> 4, nh = blockIdx.x & 15;
    const int m0 = blockIdx.y * 128, n0 = nh * 128;
    const float* bias = (z == 0) ? bq : (z == 1) ? bk : bv;
    const __half* Bm  = (z < 2) ? g_Bqk + (size_t)z*H_*H_ : g_Bf;

    float acc[4][8][4];
    hmma_mainloop_f16(g_Af, Bm, m0, n0, sb, acc);

    const int gr = lane >> 2, gc = (lane & 3)*2;
    if (z < 2) {
        __half* oq = (z == 0) ? g_qf : g_kf;
#pragma unroll
        for (int mi = 0; mi < 4; mi++)
#pragma unroll
            for (int h = 0; h < 2; h++) {
                int m = m0 + (w >> 1)*64 + mi*16 + gr + h*8;
                int bb = m >> 11, s = m & 2047;
                size_t base = ((size_t)(bb*NH_ + nh)*S_ + s) * HD_;
#pragma unroll
                for (int nj = 0; nj < 4; nj++) {
                    int c = (w & 1)*32 + nj*8 + gc;
                    float vl0 = acc[mi][nj][h*2+0]   + bias[n0 + c];
                    float vl1 = acc[mi][nj][h*2+1]   + bias[n0 + c + 1];
                    float vh0 = acc[mi][nj+4][h*2+0] + bias[n0 + 64 + c];
                    float vh1 = acc[mi][nj+4][h*2+1] + bias[n0 + 64 + c + 1];
                    float cs0 = g_cos[s*64 + c],     sn0 = g_sin[s*64 + c];
                    float cs1 = g_cos[s*64 + c + 1], sn1 = g_sin[s*64 + c + 1];
                    *(uint32_t*)&oq[base + c] =
                        packhf(vl0*cs0 - vh0*sn0, vl1*cs1 - vh1*sn1);
                    *(uint32_t*)&oq[base + 64 + c] =
                        packhf(vh0*cs0 + vl0*sn0, vh1*cs1 + vl1*sn1);
                }
            }
    } else {
#pragma unroll
        for (int mi = 0; mi < 4; mi++)
#pragma unroll
            for (int h = 0; h < 2; h++) {
                int m = m0 + (w >> 1)*64 + mi*16 + gr + h*8;
                int bb = m >> 11, s = m & 2047;
                size_t vb = (size_t)(bb*NH_ + nh) * HD_;
#pragma unroll
                for (int nj = 0; nj < 4; nj++) {
                    int c = (w & 1)*32 + nj*8 + gc;
                    float vv[4] = {acc[mi][nj][h*2+0]   + bias[n0 + c],
                                   acc[mi][nj][h*2+1]   + bias[n0 + c + 1],
                                   acc[mi][nj+4][h*2+0] + bias[n0 + 64 + c],
                                   acc[mi][nj+4][h*2+1] + bias[n0 + 64 + c + 1]};
                    int   cc[4] = {c, c + 1, 64 + c, 64 + c + 1};
#pragma unroll
                    for (int u = 0; u < 4; u++)
                        g_vtf[(vb + cc[u])*S_ + s] = __float2half_rn(vv[u]);
                }
            }
    }
}

// ---------------- output projection (fp16) ----------------------------------
__global__ __launch_bounds__(128, 2)
void gemm_out_f16(const float* __restrict__ bo, float* __restrict__ out)
{
    extern __shared__ char dsm[];
    uint32_t sb = smem_u32(dsm);
    const int tid = threadIdx.x, lane = tid & 31, w = tid >> 5;
    const int m0 = blockIdx.y * 128, n0 = blockIdx.x * 128;

    float acc[4][8][4];
    hmma_mainloop_f16(g_Af, g_Wf, m0, n0, sb, acc);

    const int gr = lane >> 2, gc = (lane & 3)*2;
#pragma unroll
    for (int mi = 0; mi < 4; mi++)
#pragma unroll
        for (int h = 0; h < 2; h++) {
            int m = m0 + (w >> 1)*64 + mi*16 + gr + h*8;
            float* op = out + (size_t)m * H_ + n0;
#pragma unroll
            for (int nj = 0; nj < 4; nj++) {
                int c = (w & 1)*32 + nj*8 + gc;
                *(float2*)&op[c] = make_float2(
                    acc[mi][nj][h*2+0] + bo[n0 + c],
                    acc[mi][nj][h*2+1] + bo[n0 + c + 1]);
                *(float2*)&op[64 + c] = make_float2(
                    acc[mi][nj+4][h*2+0] + bo[n0 + 64 + c],
                    acc[mi][nj+4][h*2+1] + bo[n0 + 64 + c + 1]);
            }
        }
}

// ---------------- tensor-core causal flash attention (all fp16) -------------
// regions: 0 Qf 1 Kf 2 Vf
#define ASTR 272
#define ARGN (128*ASTR)
#define SMEM_AT (3*ARGN)         // 104448

__device__ __forceinline__ void attn_ld(uint32_t dst,
    const __half* __restrict__ src, int stride, int tid)
{
#pragma unroll
    for (int it = 0; it < 8; it++) {
        int idx = tid + it*256;
        int r = idx >> 4, c = idx & 15;
        CP16(dst + r*ASTR + c*16, (const void*)(src + (size_t)r*stride + c*8));
    }
}

__global__ __launch_bounds__(256, 1)
void attn_tc_kernel()
{
    extern __shared__ char dsm[];
    uint32_t sb = smem_u32(dsm);
    const int tid = threadIdx.x, lane = tid & 31, wm = tid >> 5;
    const int gr = lane >> 2, gc = (lane & 3)*2;
    const int bh = blockIdx.y;
    const int iq = (int)gridDim.x - 1 - (int)blockIdx.x;
    const int laneoff = (lane & 15)*ASTR + (lane >> 4)*16;
    const float scale = 0.08838834764831845f;

    const size_t qkbase = (size_t)bh * S_ * HD_;
    const size_t vbase  = (size_t)bh * HD_ * S_;

    attn_ld(sb + 0*ARGN, g_qf + qkbase + (size_t)iq*128*HD_, HD_, tid);
    CP_COMMIT();
    attn_ld(sb + 1*ARGN, g_kf + qkbase, HD_, tid);
    CP_COMMIT();
    attn_ld(sb + 2*ARGN, g_vtf + vbase, S_, tid);
    CP_COMMIT();

    const uint32_t qfb = sb + 0*ARGN + wm*16*ASTR + laneoff;
    const uint32_t kfb = sb + 1*ARGN + laneoff;
    const uint32_t vfb = sb + 2*ARGN + laneoff;

    float O[16][4];
#pragma unroll
    for (int j = 0; j < 16; j++)
#pragma unroll
        for (int k = 0; k < 4; k++) O[j][k] = 0.f;
    float m0r = -1e30f, m1r = -1e30f, l0r = 0.f, l1r = 0.f;

    for (int jt = 0; jt <= iq; jt++) {
        asm volatile("cp.async.wait_group 1;" ::: "memory");
        __syncthreads();                       // Q + K(jt) ready

        // ---- S = Q K^T (fp16) ----
        float Sf[16][4];
#pragma unroll
        for (int j = 0; j < 16; j++)
#pragma unroll
            for (int k = 0; k < 4; k++) Sf[j][k] = 0.f;
#pragma unroll
        for (int t = 0; t < 8; t++) {
            uint32_t a[4];
            LDM4(a, qfb + t*32);
#pragma unroll
            for (int jp = 0; jp < 8; jp++) {
                uint32_t b4[4];
                LDM4(b4, kfb + jp*16*ASTR + t*32);
                mma_f16(Sf[2*jp],   a, b4[0], b4[2]);
                mma_f16(Sf[2*jp+1], a, b4[1], b4[3]);
            }
        }
        __syncthreads();
        if (jt < iq) {                         // prefetch K(jt+1)
            attn_ld(sb + 1*ARGN, g_kf + qkbase + (size_t)(jt+1)*128*HD_, HD_, tid);
            CP_COMMIT();
        }

        // ---- scale + causal mask ----
        const int r0 = wm*16 + gr, r1 = r0 + 8;
        if (jt == iq) {
#pragma unroll
            for (int j = 0; j < 16; j++) {
                int cA = j*8 + gc, cB = cA + 1;
                Sf[j][0] = (cA > r0) ? -1e30f : Sf[j][0]*scale;
                Sf[j][1] = (cB > r0) ? -1e30f : Sf[j][1]*scale;
                Sf[j][2] = (cA > r1) ? -1e30f : Sf[j][2]*scale;
                Sf[j][3] = (cB > r1) ? -1e30f : Sf[j][3]*scale;
            }
        } else {
#pragma unroll
            for (int j = 0; j < 16; j++)
#pragma unroll
                for (int k = 0; k < 4; k++) Sf[j][k] *= scale;
        }

        // ---- online softmax ----
        float mx0 = -1e30f, mx1 = -1e30f;
#pragma unroll
        for (int j = 0; j < 16; j++) {
            mx0 = fmaxf(mx0, fmaxf(Sf[j][0], Sf[j][1]));
            mx1 = fmaxf(mx1, fmaxf(Sf[j][2], Sf[j][3]));
        }
        mx0 = fmaxf(mx0, __shfl_xor_sync(0xffffffffu, mx0, 1));
        mx0 = fmaxf(mx0, __shfl_xor_sync(0xffffffffu, mx0, 2));
        mx1 = fmaxf(mx1, __shfl_xor_sync(0xffffffffu, mx1, 1));
        mx1 = fmaxf(mx1, __shfl_xor_sync(0xffffffffu, mx1, 2));
        float mn0 = fmaxf(m0r, mx0), mn1 = fmaxf(m1r, mx1);
        float al0 = __expf(m0r - mn0), al1 = __expf(m1r - mn1);
        m0r = mn0; m1r = mn1;
        float sum0 = 0.f, sum1 = 0.f;
#pragma unroll
        for (int j = 0; j < 16; j++) {
            Sf[j][0] = __expf(Sf[j][0] - mn0); sum0 += Sf[j][0];
            Sf[j][1] = __expf(Sf[j][1] - mn0); sum0 += Sf[j][1];
            Sf[j][2] = __expf(Sf[j][2] - mn1); sum1 += Sf[j][2];
            Sf[j][3] = __expf(Sf[j][3] - mn1); sum1 += Sf[j][3];
        }
        sum0 += __shfl_xor_sync(0xffffffffu, sum0, 1);
        sum0 += __shfl_xor_sync(0xffffffffu, sum0, 2);
        sum1 += __shfl_xor_sync(0xffffffffu, sum1, 1);
        sum1 += __shfl_xor_sync(0xffffffffu, sum1, 2);
        l0r = l0r*al0 + sum0; l1r = l1r*al1 + sum1;
#pragma unroll
        for (int j = 0; j < 16; j++) {
            O[j][0] *= al0; O[j][1] *= al0;
            O[j][2] *= al1; O[j][3] *= al1;
        }

        asm volatile("cp.async.wait_group 1;" ::: "memory");
        __syncthreads();                       // V(jt) ready

        // ---- O += P V (fp16) ----
#pragma unroll
        for (int t = 0; t < 8; t++) {
            uint32_t aP[4];
            aP[0] = packhf(Sf[2*t][0],   Sf[2*t][1]);
            aP[1] = packhf(Sf[2*t][2],   Sf[2*t][3]);
            aP[2] = packhf(Sf[2*t+1][0], Sf[2*t+1][1]);
            aP[3] = packhf(Sf[2*t+1][2], Sf[2*t+1][3]);
#pragma unroll
            for (int jp = 0; jp < 8; jp++) {
                uint32_t b4[4];
                LDM4(b4, vfb + jp*16*ASTR + t*32);
                mma_f16(O[2*jp],   aP, b4[0], b4[2]);
                mma_f16(O[2*jp+1], aP, b4[1], b4[3]);
            }
        }
        __syncthreads();
        if (jt < iq) {                         // prefetch V(jt+1)
            attn_ld(sb + 2*ARGN, g_vtf + vbase + (size_t)(jt+1)*128, S_, tid);
            CP_COMMIT();
        }
    }

    // ---- finalize: write fp16 g_Af directly ----
    const int b = bh >> 4, nh = bh & 15;
    float inv0 = 1.f / l0r, inv1 = 1.f / l1r;
    size_t row0 = (size_t)(b*S_ + iq*128 + wm*16 + gr);
#pragma unroll
    for (int j = 0; j < 16; j++) {
        int col = nh*HD_ + j*8 + gc;
        *(uint32_t*)&g_Af[row0*H_ + col] =
            packhf(O[j][0]*inv0, O[j][1]*inv0);
        *(uint32_t*)&g_Af[(row0 + 8)*H_ + col] =
            packhf(O[j][2]*inv1, O[j][3]*inv1);
    }
}

// ---------------- launch ----------------------------------------------------
extern "C" void kernel_launch(void* const* d_in, const int* in_sizes, int n_in,
                              void* d_out, int out_size)
{
    (void)in_sizes; (void)n_in; (void)out_size;
    const float* X  = (const float*)d_in[0];
    const float* Wq = (const float*)d_in[2];
    const float* bq = (const float*)d_in[3];
    const float* Wk = (const float*)d_in[4];
    const float* bk = (const float*)d_in[5];
    const float* Wv = (const float*)d_in[6];
    const float* bv = (const float*)d_in[7];
    const float* Wo = (const float*)d_in[8];
    const float* bo = (const float*)d_in[9];
    float* out = (float*)d_out;

    rope_table_kernel<<<(S_*64 + 255)/256, 256>>>();
    convert_f16_kernel<<<M_*H_/1024, 256>>>(X);
    transpose_f16_kernel<<<dim3(H_/32, H_/32, 4), dim3(32, 8)>>>(Wq, Wk, Wv, Wo);

    cudaFuncSetAttribute(gemm_qkv_f16, cudaFuncAttributeMaxDynamicSharedMemorySize,
                         SMEM_GF);
    gemm_qkv_f16<<<dim3(48, 32), 128, SMEM_GF>>>(bq, bk, bv);

    cudaFuncSetAttribute(attn_tc_kernel, cudaFuncAttributeMaxDynamicSharedMemorySize,
                         SMEM_AT);
    attn_tc_kernel<<<dim3(S_/128, B_*NH_), 256, SMEM_AT>>>();

    cudaFuncSetAttribute(gemm_out_f16, cudaFuncAttributeMaxDynamicSharedMemorySize,
                         SMEM_GF);
    gemm_out_f16<<<dim3(16, 32), 128, SMEM_GF>>>(bo, out);
}

// round 13
// speedup vs baseline: 1.7152x; 1.7152x over previous
#include <cuda_runtime.h>
#include <cuda_bf16.h>
#include <cuda_fp16.h>
#include <math.h>
#include <stdint.h>

#define B_  2
#define S_  2048
#define H_  2048
#define NH_ 16
#define HD_ 128
#define M_  (B_*S_)   // 4096

// ---------------- scratch (device globals) ---------------------------------
__device__ float g_cos[S_*64];
__device__ float g_sin[S_*64];

__device__ __align__(16) __half g_Af[M_*H_];          // activations fp16
__device__ __align__(16) __half g_Bqk[2*H_*H_];       // Wq^T, Wk^T fp16
__device__ __align__(16) __half g_Bf[H_*H_];          // Wv^T fp16
__device__ __align__(16) __half g_Wf[H_*H_];          // Wo^T fp16

// attention operands
__device__ __align__(16) __half g_qf[B_*NH_*S_*HD_];  // roped Q fp16
__device__ __align__(16) __half g_kf[B_*NH_*S_*HD_];  // roped K fp16
__device__ __align__(16) __half g_vtf[B_*NH_*HD_*S_]; // V^T fp16

// ---------------- PTX helpers ----------------------------------------------
__device__ __forceinline__ uint32_t smem_u32(const void* p) {
    uint32_t a;
    asm("{ .reg .u64 t; cvta.to.shared.u64 t, %1; cvt.u32.u64 %0, t; }"
        : "=r"(a) : "l"(p));
    return a;
}
#define CP16(dst, src) \
    asm volatile("cp.async.cg.shared.global [%0], [%1], 16;" \
                 :: "r"(dst), "l"(src) : "memory")
#define CP_COMMIT() asm volatile("cp.async.commit_group;" ::: "memory")

#define LDM4(r, addr) \
    asm volatile("ldmatrix.sync.aligned.m8n8.x4.shared.b16 {%0,%1,%2,%3}, [%4];" \
        : "=r"((r)[0]), "=r"((r)[1]), "=r"((r)[2]), "=r"((r)[3]) : "r"(addr))

__device__ __forceinline__ void mma_f16(float* d, const uint32_t* a,
                                        uint32_t b0, uint32_t b1) {
    asm volatile("mma.sync.aligned.m16n8k16.row.col.f32.f16.f16.f32 "
        "{%0,%1,%2,%3}, {%4,%5,%6,%7}, {%8,%9}, {%0,%1,%2,%3};"
        : "+f"(d[0]), "+f"(d[1]), "+f"(d[2]), "+f"(d[3])
        : "r"(a[0]), "r"(a[1]), "r"(a[2]), "r"(a[3]), "r"(b0), "r"(b1));
}
__device__ __forceinline__ uint32_t packhf(float x, float y) {
    __half2 t = __floats2half2_rn(x, y);
    return *(uint32_t*)&t;
}

// ---------------- prep kernels ---------------------------------------------
__global__ void rope_table_kernel()
{
    int idx = blockIdx.x * blockDim.x + threadIdx.x;
    if (idx >= S_ * 64) return;
    int s = idx >> 6, p = idx & 63;
    double invf = exp(-log(10000.0) * (double)p / 64.0);
    double ang  = (double)s * invf;
    g_cos[idx] = (float)cos(ang);
    g_sin[idx] = (float)sin(ang);
}

// fp32 X -> fp16 g_Af
__global__ void convert_f16_kernel(const float* __restrict__ in)
{
    int i = (blockIdx.x * blockDim.x + threadIdx.x) * 4;
    float4 v = *(const float4*)&in[i];
    *(ushort4*)((unsigned short*)g_Af + i) = make_ushort4(
        __half_as_ushort(__float2half_rn(v.x)),
        __half_as_ushort(__float2half_rn(v.y)),
        __half_as_ushort(__float2half_rn(v.z)),
        __half_as_ushort(__float2half_rn(v.w)));
}

// all four W [2048,2048] -> W^T fp16 in one launch (blockIdx.z selects)
__global__ void transpose_f16_kernel(const float* __restrict__ Wq,
                                     const float* __restrict__ Wk,
                                     const float* __restrict__ Wv,
                                     const float* __restrict__ Wo)
{
    int which = blockIdx.z;
    const float* in = (which == 0) ? Wq : (which == 1) ? Wk
                    : (which == 2) ? Wv : Wo;
    __half* dst = (which < 2) ? g_Bqk + (size_t)which*H_*H_
                : (which == 2) ? g_Bf : g_Wf;
    __shared__ float t[32][33];
    int tx = threadIdx.x, ty = threadIdx.y;
    int c0 = blockIdx.x * 32, r0 = blockIdx.y * 32;
#pragma unroll
    for (int k = 0; k < 4; k++)
        t[ty + 8*k][tx] = in[(size_t)(r0 + ty + 8*k) * H_ + c0 + tx];
    __syncthreads();
#pragma unroll
    for (int k = 0; k < 4; k++)
        dst[(size_t)(c0 + ty + 8*k) * H_ + r0 + tx] =
            __float2half_rn(t[tx][ty + 8*k]);
}

// ---------------- fp16 GEMM mainloop (round-10 proven config) ---------------
// CTA tile 128x128, 256 threads (8 warps), warp tile 32M x 64N (split cols).
// 64B swizzled rows: phys = r*64 + 16*(g ^ ((r>>1)&3)).
// 6 stages, one barrier per TWO 32-K chunks.
#define REG_B  8192              // 128 rows x 64B
#define FSTG_B (2*REG_B)         // A|B regions = 16384
#define SMEM_GF (6*FSTG_B)       // 98304

__device__ __forceinline__ void ld_region(uint32_t dst,
    const __half* __restrict__ src, int row0, int kb, int tid)
{
#pragma unroll
    for (int it = 0; it < 2; it++) {
        int idx = tid + it*256;           // 512 granules
        int r = idx >> 2, g = idx & 3;
        uint32_t sw = (uint32_t)((g ^ ((r >> 1) & 3)) << 4);
        CP16(dst + r*64 + sw,
             (const void*)(src + (size_t)(row0 + r) * H_ + kb + g*8));
    }
}
__device__ __forceinline__ void ld_stage_f16(uint32_t s0,
    const __half* A, const __half* Bm, int m0, int n0, int kb, int tid)
{
    ld_region(s0,         A,  m0, kb, tid);
    ld_region(s0 + REG_B, Bm, n0, kb, tid);
    CP_COMMIT();
}

__device__ __forceinline__ void hmma_mainloop_f16(
    const __half* A, const __half* Bm,
    int m0, int n0, uint32_t sb, float acc[2][8][4])
{
    const int tid = threadIdx.x, lane = tid & 31, w = tid >> 5;
#pragma unroll
    for (int i = 0; i < 2; i++)
#pragma unroll
        for (int j = 0; j < 8; j++)
#pragma unroll
            for (int k = 0; k < 4; k++) acc[i][j][k] = 0.f;

    // prologue: chunks 0..3 into slots 0..3
    ld_stage_f16(sb + 0*FSTG_B, A, Bm, m0, n0, 0,  tid);
    ld_stage_f16(sb + 1*FSTG_B, A, Bm, m0, n0, 32, tid);
    ld_stage_f16(sb + 2*FSTG_B, A, Bm, m0, n0, 64, tid);
    ld_stage_f16(sb + 3*FSTG_B, A, Bm, m0, n0, 96, tid);

    const int hi  = lane >> 4;            // 16B column select
    const int rsw = (lane >> 1) & 3;      // swizzle const (same for all rows)
    const uint32_t swz0 = (uint32_t)(((0 + hi) ^ rsw) << 4);   // kk=0
    const uint32_t swz1 = (uint32_t)(((2 + hi) ^ rsw) << 4);   // kk=1
    const uint32_t arow64 = (uint32_t)(((w >> 1)*32 + (lane & 15)) * 64);
    const uint32_t brow64 = (uint32_t)(((w & 1)*32 + (lane & 15)) * 64);

    for (int i = 0; i < 32; i++) {
        const int cA = 2*i;
        if (i < 31) asm volatile("cp.async.wait_group 2;" ::: "memory");
        else        asm volatile("cp.async.wait_group 0;" ::: "memory");
        __syncthreads();
        if (cA + 4 < 64) {
            ld_stage_f16(sb + ((cA+4)%6)*FSTG_B, A, Bm, m0, n0, (cA+4)*32, tid);
            ld_stage_f16(sb + ((cA+5)%6)*FSTG_B, A, Bm, m0, n0, (cA+5)*32, tid);
        }
#pragma unroll
        for (int cc = 0; cc < 2; cc++) {
            uint32_t s0 = sb + (uint32_t)(((cA + cc) % 6) * FSTG_B);
#pragma unroll
            for (int kk = 0; kk < 2; kk++) {
                uint32_t swz = kk ? swz1 : swz0;
                uint32_t a[2][4];
                LDM4(a[0], s0 + arow64 + swz);
                LDM4(a[1], s0 + arow64 + 1024 + swz);
#pragma unroll
                for (int p = 0; p < 4; p++) {
                    uint32_t roff = (uint32_t)(((p & 1)*16 + ((p & 2) ? 64 : 0)) * 64);
                    uint32_t q[4];
                    LDM4(q, s0 + REG_B + brow64 + roff + swz);
#pragma unroll
                    for (int mi = 0; mi < 2; mi++) {
                        mma_f16(acc[mi][2*p],   a[mi], q[0], q[2]);
                        mma_f16(acc[mi][2*p+1], a[mi], q[1], q[3]);
                    }
                }
            }
        }
    }
}

// ---------------- QKV projection + bias (+RoPE) -> fp16 ---------------------
// grid (48, 32): z = x>>4 (0=q,1=k,2=v), nh = x&15 ; y -> m-tile
__global__ __launch_bounds__(256, 2)
void gemm_qkv_f16(const float* __restrict__ bq, const float* __restrict__ bk,
                  const float* __restrict__ bv)
{
    extern __shared__ char dsm[];
    uint32_t sb = smem_u32(dsm);
    const int tid = threadIdx.x, lane = tid & 31, w = tid >> 5;
    const int z = blockIdx.x >> 4, nh = blockIdx.x & 15;
    const int m0 = blockIdx.y * 128, n0 = nh * 128;
    const float* bias = (z == 0) ? bq : (z == 1) ? bk : bv;
    const __half* Bm  = (z < 2) ? g_Bqk + (size_t)z*H_*H_ : g_Bf;

    float acc[2][8][4];
    hmma_mainloop_f16(g_Af, Bm, m0, n0, sb, acc);

    const int gr = lane >> 2, gc = (lane & 3)*2;
    if (z < 2) {
        __half* oq = (z == 0) ? g_qf : g_kf;
#pragma unroll
        for (int mi = 0; mi < 2; mi++)
#pragma unroll
            for (int h = 0; h < 2; h++) {
                int m = m0 + (w >> 1)*32 + mi*16 + gr + h*8;
                int bb = m >> 11, s = m & 2047;
                size_t base = ((size_t)(bb*NH_ + nh)*S_ + s) * HD_;
#pragma unroll
                for (int nj = 0; nj < 4; nj++) {
                    int c = (w & 1)*32 + nj*8 + gc;
                    float vl0 = acc[mi][nj][h*2+0]   + bias[n0 + c];
                    float vl1 = acc[mi][nj][h*2+1]   + bias[n0 + c + 1];
                    float vh0 = acc[mi][nj+4][h*2+0] + bias[n0 + 64 + c];
                    float vh1 = acc[mi][nj+4][h*2+1] + bias[n0 + 64 + c + 1];
                    float cs0 = g_cos[s*64 + c],     sn0 = g_sin[s*64 + c];
                    float cs1 = g_cos[s*64 + c + 1], sn1 = g_sin[s*64 + c + 1];
                    *(uint32_t*)&oq[base + c] =
                        packhf(vl0*cs0 - vh0*sn0, vl1*cs1 - vh1*sn1);
                    *(uint32_t*)&oq[base + 64 + c] =
                        packhf(vh0*cs0 + vl0*sn0, vh1*cs1 + vl1*sn1);
                }
            }
    } else {
#pragma unroll
        for (int mi = 0; mi < 2; mi++)
#pragma unroll
            for (int h = 0; h < 2; h++) {
                int m = m0 + (w >> 1)*32 + mi*16 + gr + h*8;
                int bb = m >> 11, s = m & 2047;
                size_t vb = (size_t)(bb*NH_ + nh) * HD_;
#pragma unroll
                for (int nj = 0; nj < 4; nj++) {
                    int c = (w & 1)*32 + nj*8 + gc;
                    float vv[4] = {acc[mi][nj][h*2+0]   + bias[n0 + c],
                                   acc[mi][nj][h*2+1]   + bias[n0 + c + 1],
                                   acc[mi][nj+4][h*2+0] + bias[n0 + 64 + c],
                                   acc[mi][nj+4][h*2+1] + bias[n0 + 64 + c + 1]};
                    int   cc[4] = {c, c + 1, 64 + c, 64 + c + 1};
#pragma unroll
                    for (int u = 0; u < 4; u++)
                        g_vtf[(vb + cc[u])*S_ + s] = __float2half_rn(vv[u]);
                }
            }
    }
}

// ---------------- output projection (fp16) ----------------------------------
__global__ __launch_bounds__(256, 2)
void gemm_out_f16(const float* __restrict__ bo, float* __restrict__ out)
{
    extern __shared__ char dsm[];
    uint32_t sb = smem_u32(dsm);
    const int tid = threadIdx.x, lane = tid & 31, w = tid >> 5;
    const int m0 = blockIdx.y * 128, n0 = blockIdx.x * 128;

    float acc[2][8][4];
    hmma_mainloop_f16(g_Af, g_Wf, m0, n0, sb, acc);

    const int gr = lane >> 2, gc = (lane & 3)*2;
#pragma unroll
    for (int mi = 0; mi < 2; mi++)
#pragma unroll
        for (int h = 0; h < 2; h++) {
            int m = m0 + (w >> 1)*32 + mi*16 + gr + h*8;
            float* op = out + (size_t)m * H_ + n0;
#pragma unroll
            for (int nj = 0; nj < 4; nj++) {
                int c = (w & 1)*32 + nj*8 + gc;
                *(float2*)&op[c] = make_float2(
                    acc[mi][nj][h*2+0] + bo[n0 + c],
                    acc[mi][nj][h*2+1] + bo[n0 + c + 1]);
                *(float2*)&op[64 + c] = make_float2(
                    acc[mi][nj+4][h*2+0] + bo[n0 + 64 + c],
                    acc[mi][nj+4][h*2+1] + bo[n0 + 64 + c + 1]);
            }
        }
}

// ---------------- tensor-core causal flash attention (all fp16) -------------
// grid (bh=32, iq_rev=16): iq on the SLOW axis, reversed -> global heavy-first
// (LPT) scheduling across the 3.5 waves. regions: 0 Qf 1 Kf 2 Vf.
#define ASTR 272
#define ARGN (128*ASTR)
#define SMEM_AT (3*ARGN)         // 104448

__device__ __forceinline__ void attn_ld(uint32_t dst,
    const __half* __restrict__ src, int stride, int tid)
{
#pragma unroll
    for (int it = 0; it < 8; it++) {
        int idx = tid + it*256;
        int r = idx >> 4, c = idx & 15;
        CP16(dst + r*ASTR + c*16, (const void*)(src + (size_t)r*stride + c*8));
    }
}

__global__ __launch_bounds__(256, 1)
void attn_tc_kernel()
{
    extern __shared__ char dsm[];
    uint32_t sb = smem_u32(dsm);
    const int tid = threadIdx.x, lane = tid & 31, wm = tid >> 5;
    const int gr = lane >> 2, gc = (lane & 3)*2;
    const int bh = blockIdx.x;
    const int iq = (int)gridDim.y - 1 - (int)blockIdx.y;
    const int laneoff = (lane & 15)*ASTR + (lane >> 4)*16;
    // scale * log2(e): softmax done in exp2 domain (MUFU.EX2 direct)
    const float scale2 = 0.08838834764831845f * 1.4426950408889634f;

    const size_t qkbase = (size_t)bh * S_ * HD_;
    const size_t vbase  = (size_t)bh * HD_ * S_;

    attn_ld(sb + 0*ARGN, g_qf + qkbase + (size_t)iq*128*HD_, HD_, tid);
    CP_COMMIT();
    attn_ld(sb + 1*ARGN, g_kf + qkbase, HD_, tid);
    CP_COMMIT();
    attn_ld(sb + 2*ARGN, g_vtf + vbase, S_, tid);
    CP_COMMIT();

    const uint32_t qfb = sb + 0*ARGN + wm*16*ASTR + laneoff;
    const uint32_t kfb = sb + 1*ARGN + laneoff;
    const uint32_t vfb = sb + 2*ARGN + laneoff;

    float O[16][4];
#pragma unroll
    for (int j = 0; j < 16; j++)
#pragma unroll
        for (int k = 0; k < 4; k++) O[j][k] = 0.f;
    float m0r = -1e30f, m1r = -1e30f, l0r = 0.f, l1r = 0.f;

    for (int jt = 0; jt <= iq; jt++) {
        asm volatile("cp.async.wait_group 1;" ::: "memory");
        __syncthreads();                       // Q + K(jt) ready

        // ---- S = Q K^T (fp16) ----
        float Sf[16][4];
#pragma unroll
        for (int j = 0; j < 16; j++)
#pragma unroll
            for (int k = 0; k < 4; k++) Sf[j][k] = 0.f;
#pragma unroll
        for (int t = 0; t < 8; t++) {
            uint32_t a[4];
            LDM4(a, qfb + t*32);
#pragma unroll
            for (int jp = 0; jp < 8; jp++) {
                uint32_t b4[4];
                LDM4(b4, kfb + jp*16*ASTR + t*32);
                mma_f16(Sf[2*jp],   a, b4[0], b4[2]);
                mma_f16(Sf[2*jp+1], a, b4[1], b4[3]);
            }
        }
        __syncthreads();
        if (jt < iq) {                         // prefetch K(jt+1)
            attn_ld(sb + 1*ARGN, g_kf + qkbase + (size_t)(jt+1)*128*HD_, HD_, tid);
            CP_COMMIT();
        }

        // ---- scale (exp2 domain) + causal mask ----
        const int r0 = wm*16 + gr, r1 = r0 + 8;
        if (jt == iq) {
#pragma unroll
            for (int j = 0; j < 16; j++) {
                int cA = j*8 + gc, cB = cA + 1;
                Sf[j][0] = (cA > r0) ? -1e30f : Sf[j][0]*scale2;
                Sf[j][1] = (cB > r0) ? -1e30f : Sf[j][1]*scale2;
                Sf[j][2] = (cA > r1) ? -1e30f : Sf[j][2]*scale2;
                Sf[j][3] = (cB > r1) ? -1e30f : Sf[j][3]*scale2;
            }
        } else {
#pragma unroll
            for (int j = 0; j < 16; j++)
#pragma unroll
                for (int k = 0; k < 4; k++) Sf[j][k] *= scale2;
        }

        // ---- online softmax (base-2) ----
        float mx0 = -1e30f, mx1 = -1e30f;
#pragma unroll
        for (int j = 0; j < 16; j++) {
            mx0 = fmaxf(mx0, fmaxf(Sf[j][0], Sf[j][1]));
            mx1 = fmaxf(mx1, fmaxf(Sf[j][2], Sf[j][3]));
        }
        mx0 = fmaxf(mx0, __shfl_xor_sync(0xffffffffu, mx0, 1));
        mx0 = fmaxf(mx0, __shfl_xor_sync(0xffffffffu, mx0, 2));
        mx1 = fmaxf(mx1, __shfl_xor_sync(0xffffffffu, mx1, 1));
        mx1 = fmaxf(mx1, __shfl_xor_sync(0xffffffffu, mx1, 2));
        float mn0 = fmaxf(m0r, mx0), mn1 = fmaxf(m1r, mx1);
        float al0 = exp2f(m0r - mn0), al1 = exp2f(m1r - mn1);
        m0r = mn0; m1r = mn1;
        float sum0 = 0.f, sum1 = 0.f;
#pragma unroll
        for (int j = 0; j < 16; j++) {
            Sf[j][0] = exp2f(Sf[j][0] - mn0); sum0 += Sf[j][0];
            Sf[j][1] = exp2f(Sf[j][1] - mn0); sum0 += Sf[j][1];
            Sf[j][2] = exp2f(Sf[j][2] - mn1); sum1 += Sf[j][2];
            Sf[j][3] = exp2f(Sf[j][3] - mn1); sum1 += Sf[j][3];
        }
        sum0 += __shfl_xor_sync(0xffffffffu, sum0, 1);
        sum0 += __shfl_xor_sync(0xffffffffu, sum0, 2);
        sum1 += __shfl_xor_sync(0xffffffffu, sum1, 1);
        sum1 += __shfl_xor_sync(0xffffffffu, sum1, 2);
        l0r = l0r*al0 + sum0; l1r = l1r*al1 + sum1;
#pragma unroll
        for (int j = 0; j < 16; j++) {
            O[j][0] *= al0; O[j][1] *= al0;
            O[j][2] *= al1; O[j][3] *= al1;
        }

        asm volatile("cp.async.wait_group 1;" ::: "memory");
        __syncthreads();                       // V(jt) ready

        // ---- O += P V (fp16) ----
#pragma unroll
        for (int t = 0; t < 8; t++) {
            uint32_t aP[4];
            aP[0] = packhf(Sf[2*t][0],   Sf[2*t][1]);
            aP[1] = packhf(Sf[2*t][2],   Sf[2*t][3]);
            aP[2] = packhf(Sf[2*t+1][0], Sf[2*t+1][1]);
            aP[3] = packhf(Sf[2*t+1][2], Sf[2*t+1][3]);
#pragma unroll
            for (int jp = 0; jp < 8; jp++) {
                uint32_t b4[4];
                LDM4(b4, vfb + jp*16*ASTR + t*32);
                mma_f16(O[2*jp],   aP, b4[0], b4[2]);
                mma_f16(O[2*jp+1], aP, b4[1], b4[3]);
            }
        }
        __syncthreads();
        if (jt < iq) {                         // prefetch V(jt+1)
            attn_ld(sb + 2*ARGN, g_vtf + vbase + (size_t)(jt+1)*128, S_, tid);
            CP_COMMIT();
        }
    }

    // ---- finalize: write fp16 g_Af directly ----
    const int b = bh >> 4, nh = bh & 15;
    float inv0 = 1.f / l0r, inv1 = 1.f / l1r;
    size_t row0 = (size_t)(b*S_ + iq*128 + wm*16 + gr);
#pragma unroll
    for (int j = 0; j < 16; j++) {
        int col = nh*HD_ + j*8 + gc;
        *(uint32_t*)&g_Af[row0*H_ + col] =
            packhf(O[j][0]*inv0, O[j][1]*inv0);
        *(uint32_t*)&g_Af[(row0 + 8)*H_ + col] =
            packhf(O[j][2]*inv1, O[j][3]*inv1);
    }
}

// ---------------- launch ----------------------------------------------------
extern "C" void kernel_launch(void* const* d_in, const int* in_sizes, int n_in,
                              void* d_out, int out_size)
{
    (void)in_sizes; (void)n_in; (void)out_size;
    const float* X  = (const float*)d_in[0];
    const float* Wq = (const float*)d_in[2];
    const float* bq = (const float*)d_in[3];
    const float* Wk = (const float*)d_in[4];
    const float* bk = (const float*)d_in[5];
    const float* Wv = (const float*)d_in[6];
    const float* bv = (const float*)d_in[7];
    const float* Wo = (const float*)d_in[8];
    const float* bo = (const float*)d_in[9];
    float* out = (float*)d_out;

    rope_table_kernel<<<(S_*64 + 255)/256, 256>>>();
    convert_f16_kernel<<<M_*H_/1024, 256>>>(X);
    transpose_f16_kernel<<<dim3(H_/32, H_/32, 4), dim3(32, 8)>>>(Wq, Wk, Wv, Wo);

    cudaFuncSetAttribute(gemm_qkv_f16, cudaFuncAttributeMaxDynamicSharedMemorySize,
                         SMEM_GF);
    gemm_qkv_f16<<<dim3(48, 32), 256, SMEM_GF>>>(bq, bk, bv);

    cudaFuncSetAttribute(attn_tc_kernel, cudaFuncAttributeMaxDynamicSharedMemorySize,
                         SMEM_AT);
    attn_tc_kernel<<<dim3(B_*NH_, S_/128), 256, SMEM_AT>>>();

    cudaFuncSetAttribute(gemm_out_f16, cudaFuncAttributeMaxDynamicSharedMemorySize,
                         SMEM_GF);
    gemm_out_f16<<<dim3(16, 32), 256, SMEM_GF>>>(bo, out);
}